// round 2
// baseline (speedup 1.0000x reference)
#include <cuda_runtime.h>

#define NUM_USERS 50000
#define NUM_ITEMS 50000
#define D 64
#define DV 16                       // float4 chunks per 64-float node row
#define N_NODES (NUM_USERS + NUM_ITEMS)
#define N_EDGES 500000
#define NNZ_G 1000000
#define NNZ_GX 2000000
#define BATCH 8192

// ---- static device scratch (no allocation allowed) ----
__device__ float g_A[(size_t)N_NODES * D];    // current node embeddings
__device__ float g_B[(size_t)N_NODES * D];    // G * A (post g-spmm)
__device__ float g_U[(size_t)N_NODES * D];    // upd accumulator
__device__ float g_acc[(size_t)N_NODES * D];  // sum of per-layer embeddings
__device__ float g_deg[N_NODES];

// fire-and-forget vector reduction (RED.E.ADD.F32x4), sm_90+
__device__ __forceinline__ void red_add_f32x4(float4* addr, float4 v) {
    asm volatile("red.global.add.v4.f32 [%0], {%1, %2, %3, %4};"
                 :: "l"(addr), "f"(v.x), "f"(v.y), "f"(v.z), "f"(v.w)
                 : "memory");
}

// init: A = concat(user_emb, item_emb), acc = 0, deg = 0
__global__ void k_init(const float* __restrict__ ue, const float* __restrict__ ie) {
    int t = blockIdx.x * blockDim.x + threadIdx.x;
    if (t >= N_NODES * DV) return;
    float4 v;
    if (t < NUM_USERS * DV) v = ((const float4*)ue)[t];
    else                    v = ((const float4*)ie)[t - NUM_USERS * DV];
    ((float4*)g_A)[t]   = v;
    ((float4*)g_acc)[t] = make_float4(0.f, 0.f, 0.f, 0.f);
    if (t < N_NODES) g_deg[t] = 0.f;
}

// degree = bincount(train_users) + bincount(50000 + train_items)
__global__ void k_deg(const int* __restrict__ tu, const int* __restrict__ ti) {
    int e = blockIdx.x * blockDim.x + threadIdx.x;
    if (e >= N_EDGES) return;
    atomicAdd(&g_deg[tu[e]], 1.f);
    atomicAdd(&g_deg[NUM_USERS + ti[e]], 1.f);
}

// zero B and U for the next layer
__global__ void k_zero_BU() {
    int t = blockIdx.x * blockDim.x + threadIdx.x;
    if (t >= N_NODES * DV) return;
    float4 z = make_float4(0.f, 0.f, 0.f, 0.f);
    ((float4*)g_B)[t] = z;
    ((float4*)g_U)[t] = z;
}

// B[r] += v * A[c]   (COO spmm over node graph), 16 float4 chunks per nnz
__global__ void k_spmm_g(const int* __restrict__ rows, const int* __restrict__ cols,
                         const float* __restrict__ vals) {
    int t = blockIdx.x * blockDim.x + threadIdx.x;   // < NNZ_G * 16 = 16M
    int k = t >> 4;
    int j = t & 15;
    if (k >= NNZ_G) return;
    int r = rows[k], c = cols[k];
    float v = vals[k];
    float4 x = ((const float4*)g_A)[c * DV + j];
    float4 y = make_float4(v * x.x, v * x.y, v * x.z, v * x.w);
    red_add_f32x4(((float4*)g_B) + r * DV + j, y);
}

// Fused edge pipeline:
//   for each gx nnz k with e_out=gx_rows[k], c=gx_cols[k], v=gx_vals[k]:
//     U[tu[e_out]]          += v * (B[tu[c]]          (+ cat_low  on layer 0))
//     U[50000 + ti[e_out]]  += v * (B[50000 + ti[c]]  (+ cat_high on layer 0))
// warp layout: lanes 0-15 = user half (chunks 0-15), lanes 16-31 = item half.
__global__ void k_gx(const int* __restrict__ gxr, const int* __restrict__ gxc,
                     const float* __restrict__ gxv,
                     const int* __restrict__ tu, const int* __restrict__ ti,
                     const int* __restrict__ i2c, const float* __restrict__ cat,
                     int layer0) {
    int t = blockIdx.x * blockDim.x + threadIdx.x;   // < NNZ_GX * 32 = 64M
    int k = t >> 5;
    if (k >= NNZ_GX) return;
    int lane = t & 31;
    int half = lane >> 4;
    int j    = lane & 15;

    int e_out = gxr[k];
    int c     = gxc[k];
    float v   = gxv[k];

    int src_node, dst_node;
    if (half == 0) { src_node = tu[c];             dst_node = tu[e_out]; }
    else           { src_node = NUM_USERS + ti[c]; dst_node = NUM_USERS + ti[e_out]; }

    float4 x = ((const float4*)g_B)[src_node * DV + j];
    if (layer0) {
        int cidx = i2c[ti[c]];
        float4 cc = ((const float4*)cat)[cidx * 32 + lane];  // 128-float cat row
        x.x += cc.x; x.y += cc.y; x.z += cc.z; x.w += cc.w;
    }
    float4 y = make_float4(v * x.x, v * x.y, v * x.z, v * x.w);
    red_add_f32x4(((float4*)g_U) + dst_node * DV + j, y);
}

// A = 0.5 * (U / (deg + 1e-9) + B);  acc += A
__global__ void k_combine() {
    int t = blockIdx.x * blockDim.x + threadIdx.x;
    if (t >= N_NODES * DV) return;
    int n = t >> 4;
    float inv = 0.5f / (g_deg[n] + 1e-9f);
    float4 u = ((const float4*)g_U)[t];
    float4 b = ((const float4*)g_B)[t];
    float4 a;
    a.x = u.x * inv + 0.5f * b.x;
    a.y = u.y * inv + 0.5f * b.y;
    a.z = u.z * inv + 0.5f * b.z;
    a.w = u.w * inv + 0.5f * b.w;
    ((float4*)g_A)[t] = a;
    float4 ac = ((float4*)g_acc)[t];
    ac.x += a.x; ac.y += a.y; ac.z += a.z; ac.w += a.w;
    ((float4*)g_acc)[t] = ac;
}

// gamma[b] = dot(acc[users[b]], acc[50000+items[b]]) / 9   (mean over 3 layers)
__global__ void k_dot(const int* __restrict__ users, const int* __restrict__ items,
                      float* __restrict__ out) {
    int t = blockIdx.x * blockDim.x + threadIdx.x;
    int b = t >> 5;
    if (b >= BATCH) return;
    int lane = t & 31;
    const float2* au = (const float2*)(g_acc + (size_t)users[b] * D);
    const float2* ai = (const float2*)(g_acc + (size_t)(NUM_USERS + items[b]) * D);
    float2 x = au[lane], y = ai[lane];
    float s = x.x * y.x + x.y * y.y;
    #pragma unroll
    for (int o = 16; o; o >>= 1) s += __shfl_down_sync(0xffffffffu, s, o);
    if (lane == 0) out[b] = s * (1.f / 9.f);
}

extern "C" void kernel_launch(void* const* d_in, const int* in_sizes, int n_in,
                              void* d_out, int out_size) {
    const float* user_emb = (const float*)d_in[0];
    const float* item_emb = (const float*)d_in[1];
    const float* cat_emb  = (const float*)d_in[2];
    const float* g_vals   = (const float*)d_in[3];
    const float* gx_vals  = (const float*)d_in[4];
    const int*   g_rows   = (const int*)d_in[5];
    const int*   g_cols   = (const int*)d_in[6];
    const int*   gx_rows  = (const int*)d_in[7];
    const int*   gx_cols  = (const int*)d_in[8];
    const int*   tu       = (const int*)d_in[9];
    const int*   ti       = (const int*)d_in[10];
    const int*   i2c      = (const int*)d_in[11];
    const int*   users    = (const int*)d_in[12];
    const int*   items    = (const int*)d_in[13];
    float* out = (float*)d_out;

    const int TB = 256;
    int node_grid = (N_NODES * DV + TB - 1) / TB;        // 6250
    int deg_grid  = (N_EDGES + TB - 1) / TB;             // 1954
    int g_grid    = (NNZ_G * 16) / TB;                   // 62500
    int gx_grid   = (NNZ_GX * 32) / TB;                  // 250000
    int dot_grid  = (BATCH * 32 + TB - 1) / TB;          // 1024

    k_init<<<node_grid, TB>>>(user_emb, item_emb);
    k_deg<<<deg_grid, TB>>>(tu, ti);

    for (int L = 0; L < 3; ++L) {
        k_zero_BU<<<node_grid, TB>>>();
        k_spmm_g<<<g_grid, TB>>>(g_rows, g_cols, g_vals);
        k_gx<<<gx_grid, TB>>>(gx_rows, gx_cols, gx_vals, tu, ti, i2c, cat_emb,
                              (L == 0) ? 1 : 0);
        k_combine<<<node_grid, TB>>>();
    }
    k_dot<<<dot_grid, TB>>>(users, items, out);
}

// round 3
// speedup vs baseline: 1.4847x; 1.4847x over previous
#include <cuda_runtime.h>

#define NUM_USERS 50000
#define NUM_ITEMS 50000
#define D 64
#define DV 16                       // float4 chunks per 64-float node row
#define N_NODES (NUM_USERS + NUM_ITEMS)
#define N_EDGES 500000
#define NNZ_G 1000000
#define NNZ_GX 2000000
#define BATCH 8192

// ---- static device scratch (no allocation allowed) ----
__device__ float g_A[(size_t)N_NODES * D];    // current node embeddings
__device__ float g_B[(size_t)N_NODES * D];    // G * A (post g-spmm)
__device__ float g_U[(size_t)N_NODES * D];    // upd accumulator
__device__ float g_acc[(size_t)N_NODES * D];  // sum of per-layer embeddings
__device__ float g_deg[N_NODES];
__device__ int4  g_idx[NNZ_GX];               // (src_u, dst_u, src_i, dst_i), item side pre-offset
__device__ int   g_cidx[NNZ_GX];              // category row per nnz (layer 0)

// fire-and-forget vector reduction (RED.E.ADD.F32x4), sm_90+
__device__ __forceinline__ void red_add_f32x4(float4* addr, float4 v) {
    asm volatile("red.global.add.v4.f32 [%0], {%1, %2, %3, %4};"
                 :: "l"(addr), "f"(v.x), "f"(v.y), "f"(v.z), "f"(v.w)
                 : "memory");
}

// init: A = concat(user_emb, item_emb), acc = B = U = 0, deg = 0
__global__ void k_init(const float* __restrict__ ue, const float* __restrict__ ie) {
    int t = blockIdx.x * blockDim.x + threadIdx.x;
    if (t >= N_NODES * DV) return;
    float4 v;
    if (t < NUM_USERS * DV) v = ((const float4*)ue)[t];
    else                    v = ((const float4*)ie)[t - NUM_USERS * DV];
    float4 z = make_float4(0.f, 0.f, 0.f, 0.f);
    ((float4*)g_A)[t]   = v;
    ((float4*)g_acc)[t] = z;
    ((float4*)g_B)[t]   = z;
    ((float4*)g_U)[t]   = z;
    if (t < N_NODES) g_deg[t] = 0.f;
}

// degree = bincount(train_users) + bincount(50000 + train_items)
__global__ void k_deg(const int* __restrict__ tu, const int* __restrict__ ti) {
    int e = blockIdx.x * blockDim.x + threadIdx.x;
    if (e >= N_EDGES) return;
    atomicAdd(&g_deg[tu[e]], 1.f);
    atomicAdd(&g_deg[NUM_USERS + ti[e]], 1.f);
}

// hoist double indirection: done once per call, consumed 3x by k_gx
__global__ void k_prep(const int* __restrict__ gxr, const int* __restrict__ gxc,
                       const int* __restrict__ tu, const int* __restrict__ ti,
                       const int* __restrict__ i2c) {
    int e = blockIdx.x * blockDim.x + threadIdx.x;
    if (e >= NNZ_GX) return;
    int r = gxr[e];
    int c = gxc[e];
    int tuc = tu[c], tic = ti[c];
    int tur = tu[r], tir = ti[r];
    g_idx[e]  = make_int4(tuc, tur, NUM_USERS + tic, NUM_USERS + tir);
    g_cidx[e] = i2c[tic];
}

// B[r] += v * A[c]   (COO spmm over node graph), 16 float4 chunks per nnz
__global__ void __launch_bounds__(256) k_spmm_g(const int* __restrict__ rows,
                                                const int* __restrict__ cols,
                                                const float* __restrict__ vals) {
    int t = blockIdx.x * blockDim.x + threadIdx.x;   // < NNZ_G * 16 = 16M
    int k = t >> 4;
    int j = t & 15;
    if (k >= NNZ_G) return;
    int r = rows[k], c = cols[k];
    float v = vals[k];
    float4 x = ((const float4*)g_A)[c * DV + j];
    float4 y = make_float4(v * x.x, v * x.y, v * x.z, v * x.w);
    red_add_f32x4(((float4*)g_B) + r * DV + j, y);
}

// Fused edge pipeline (both halves per thread for MLP):
//   U[dst_u] += v * (B[src_u] (+ cat_low  on layer 0))
//   U[dst_i] += v * (B[src_i] (+ cat_high on layer 0))
// thread = (nnz k, chunk j); 16 threads per nnz.
template <int LAYER0>
__global__ void __launch_bounds__(256) k_gx(const float* __restrict__ gxv,
                                            const float* __restrict__ cat) {
    int t = blockIdx.x * blockDim.x + threadIdx.x;   // < NNZ_GX * 16 = 32M
    int k = t >> 4;
    int j = t & 15;
    if (k >= NNZ_GX) return;

    int4 idx = g_idx[k];
    float v  = gxv[k];

    const float4* Bv = (const float4*)g_B;
    float4 x0 = Bv[idx.x * DV + j];     // user half source
    float4 x1 = Bv[idx.z * DV + j];     // item half source

    if (LAYER0) {
        int cidx = g_cidx[k];
        const float4* cv = (const float4*)cat + cidx * 32;
        float4 c0 = cv[j];
        float4 c1 = cv[16 + j];
        x0.x += c0.x; x0.y += c0.y; x0.z += c0.z; x0.w += c0.w;
        x1.x += c1.x; x1.y += c1.y; x1.z += c1.z; x1.w += c1.w;
    }
    float4 y0 = make_float4(v * x0.x, v * x0.y, v * x0.z, v * x0.w);
    float4 y1 = make_float4(v * x1.x, v * x1.y, v * x1.z, v * x1.w);
    red_add_f32x4(((float4*)g_U) + idx.y * DV + j, y0);
    red_add_f32x4(((float4*)g_U) + idx.w * DV + j, y1);
}

// A = 0.5 * (U / (deg + 1e-9) + B);  acc += A;  then zero B,U for next layer
__global__ void k_combine() {
    int t = blockIdx.x * blockDim.x + threadIdx.x;
    if (t >= N_NODES * DV) return;
    int n = t >> 4;
    float inv = 0.5f / (g_deg[n] + 1e-9f);
    float4 u = ((const float4*)g_U)[t];
    float4 b = ((const float4*)g_B)[t];
    float4 a;
    a.x = u.x * inv + 0.5f * b.x;
    a.y = u.y * inv + 0.5f * b.y;
    a.z = u.z * inv + 0.5f * b.z;
    a.w = u.w * inv + 0.5f * b.w;
    ((float4*)g_A)[t] = a;
    float4 ac = ((float4*)g_acc)[t];
    ac.x += a.x; ac.y += a.y; ac.z += a.z; ac.w += a.w;
    ((float4*)g_acc)[t] = ac;
    float4 z = make_float4(0.f, 0.f, 0.f, 0.f);
    ((float4*)g_B)[t] = z;
    ((float4*)g_U)[t] = z;
}

// gamma[b] = dot(acc[users[b]], acc[50000+items[b]]) / 9   (mean over 3 layers)
__global__ void k_dot(const int* __restrict__ users, const int* __restrict__ items,
                      float* __restrict__ out) {
    int t = blockIdx.x * blockDim.x + threadIdx.x;
    int b = t >> 5;
    if (b >= BATCH) return;
    int lane = t & 31;
    const float2* au = (const float2*)(g_acc + (size_t)users[b] * D);
    const float2* ai = (const float2*)(g_acc + (size_t)(NUM_USERS + items[b]) * D);
    float2 x = au[lane], y = ai[lane];
    float s = x.x * y.x + x.y * y.y;
    #pragma unroll
    for (int o = 16; o; o >>= 1) s += __shfl_down_sync(0xffffffffu, s, o);
    if (lane == 0) out[b] = s * (1.f / 9.f);
}

extern "C" void kernel_launch(void* const* d_in, const int* in_sizes, int n_in,
                              void* d_out, int out_size) {
    const float* user_emb = (const float*)d_in[0];
    const float* item_emb = (const float*)d_in[1];
    const float* cat_emb  = (const float*)d_in[2];
    const float* g_vals   = (const float*)d_in[3];
    const float* gx_vals  = (const float*)d_in[4];
    const int*   g_rows   = (const int*)d_in[5];
    const int*   g_cols   = (const int*)d_in[6];
    const int*   gx_rows  = (const int*)d_in[7];
    const int*   gx_cols  = (const int*)d_in[8];
    const int*   tu       = (const int*)d_in[9];
    const int*   ti       = (const int*)d_in[10];
    const int*   i2c      = (const int*)d_in[11];
    const int*   users    = (const int*)d_in[12];
    const int*   items    = (const int*)d_in[13];
    float* out = (float*)d_out;

    const int TB = 256;
    int node_grid = (N_NODES * DV + TB - 1) / TB;        // 6250
    int deg_grid  = (N_EDGES + TB - 1) / TB;             // 1954
    int prep_grid = (NNZ_GX + TB - 1) / TB;              // 7813
    int g_grid    = (NNZ_G * 16) / TB;                   // 62500
    int gx_grid   = (NNZ_GX * 16) / TB;                  // 125000
    int dot_grid  = (BATCH * 32 + TB - 1) / TB;          // 1024

    k_init<<<node_grid, TB>>>(user_emb, item_emb);
    k_deg<<<deg_grid, TB>>>(tu, ti);
    k_prep<<<prep_grid, TB>>>(gx_rows, gx_cols, tu, ti, i2c);

    for (int L = 0; L < 3; ++L) {
        k_spmm_g<<<g_grid, TB>>>(g_rows, g_cols, g_vals);
        if (L == 0) k_gx<1><<<gx_grid, TB>>>(gx_vals, cat_emb);
        else        k_gx<0><<<gx_grid, TB>>>(gx_vals, cat_emb);
        k_combine<<<node_grid, TB>>>();
    }
    k_dot<<<dot_grid, TB>>>(users, items, out);
}

// round 4
// speedup vs baseline: 1.5240x; 1.0265x over previous
#include <cuda_runtime.h>

#define NUM_USERS 50000
#define NUM_ITEMS 50000
#define D 64
#define DV 16                       // float4 chunks per 64-float node row
#define N_NODES (NUM_USERS + NUM_ITEMS)
#define N_EDGES 500000
#define NNZ_G 1000000
#define NNZ_GX 2000000
#define BATCH 8192

// ---- static device scratch (no allocation allowed) ----
__device__ float g_A[(size_t)N_NODES * D];    // current node embeddings
__device__ float g_B[(size_t)N_NODES * D];    // G * A (post g-spmm)
__device__ float g_U[(size_t)N_NODES * D];    // upd accumulator
__device__ float g_acc[(size_t)N_NODES * D];  // sum of per-layer embeddings
__device__ float g_deg[N_NODES];
__device__ int4  g_idx[NNZ_GX];               // (src_u, dst_u, src_i, dst_i), item side pre-offset
__device__ int   g_cidx[NNZ_GX];              // category row per nnz (layer 0)

// fire-and-forget vector reduction (RED.E.ADD.F32x4), sm_90+
__device__ __forceinline__ void red_add_f32x4(float4* addr, float4 v) {
    asm volatile("red.global.add.v4.f32 [%0], {%1, %2, %3, %4};"
                 :: "l"(addr), "f"(v.x), "f"(v.y), "f"(v.z), "f"(v.w)
                 : "memory");
}

// init: A = concat(user_emb, item_emb), acc = B = U = 0, deg = 0
__global__ void k_init(const float* __restrict__ ue, const float* __restrict__ ie) {
    int t = blockIdx.x * blockDim.x + threadIdx.x;
    if (t >= N_NODES * DV) return;
    float4 v;
    if (t < NUM_USERS * DV) v = ((const float4*)ue)[t];
    else                    v = ((const float4*)ie)[t - NUM_USERS * DV];
    float4 z = make_float4(0.f, 0.f, 0.f, 0.f);
    ((float4*)g_A)[t]   = v;
    ((float4*)g_acc)[t] = z;
    ((float4*)g_B)[t]   = z;
    ((float4*)g_U)[t]   = z;
    if (t < N_NODES) g_deg[t] = 0.f;
}

// degree = bincount(train_users) + bincount(50000 + train_items)
__global__ void k_deg(const int* __restrict__ tu, const int* __restrict__ ti) {
    int e = blockIdx.x * blockDim.x + threadIdx.x;
    if (e >= N_EDGES) return;
    atomicAdd(&g_deg[tu[e]], 1.f);
    atomicAdd(&g_deg[NUM_USERS + ti[e]], 1.f);
}

// hoist double indirection: done once per call, consumed 3x by k_gx
__global__ void k_prep(const int* __restrict__ gxr, const int* __restrict__ gxc,
                       const int* __restrict__ tu, const int* __restrict__ ti,
                       const int* __restrict__ i2c) {
    int e = blockIdx.x * blockDim.x + threadIdx.x;
    if (e >= NNZ_GX) return;
    int r = gxr[e];
    int c = gxc[e];
    int tuc = tu[c], tic = ti[c];
    int tur = tu[r], tir = ti[r];
    g_idx[e]  = make_int4(tuc, tur, NUM_USERS + tic, NUM_USERS + tir);
    g_cidx[e] = i2c[tic];
}

// B[r] += v * A[c]   — 2 nnz per thread, 2 independent gather+RED chains
__global__ void __launch_bounds__(256) k_spmm_g(const int* __restrict__ rows,
                                                const int* __restrict__ cols,
                                                const float* __restrict__ vals) {
    int t = blockIdx.x * blockDim.x + threadIdx.x;   // < NNZ_G/2 * 16 = 8M
    int p = t >> 4;                                  // pair index
    int j = t & 15;
    if (p >= NNZ_G / 2) return;
    int2   r2 = ((const int2*)rows)[p];
    int2   c2 = ((const int2*)cols)[p];
    float2 v2 = ((const float2*)vals)[p];
    const float4* Av = (const float4*)g_A;
    float4 x0 = Av[c2.x * DV + j];
    float4 x1 = Av[c2.y * DV + j];
    float4 y0 = make_float4(v2.x * x0.x, v2.x * x0.y, v2.x * x0.z, v2.x * x0.w);
    float4 y1 = make_float4(v2.y * x1.x, v2.y * x1.y, v2.y * x1.z, v2.y * x1.w);
    red_add_f32x4(((float4*)g_B) + r2.x * DV + j, y0);
    red_add_f32x4(((float4*)g_B) + r2.y * DV + j, y1);
}

// Fused edge pipeline — 2 nnz per thread, 4 independent gather+RED chains:
//   U[dst_u] += v * (B[src_u] (+ cat_low  on layer 0))
//   U[dst_i] += v * (B[src_i] (+ cat_high on layer 0))
template <int LAYER0>
__global__ void __launch_bounds__(256) k_gx(const float* __restrict__ gxv,
                                            const float* __restrict__ cat) {
    int t = blockIdx.x * blockDim.x + threadIdx.x;   // < NNZ_GX/2 * 16 = 16M
    int p = t >> 4;
    int j = t & 15;
    if (p >= NNZ_GX / 2) return;
    int k0 = p * 2;

    int4 ia = g_idx[k0];
    int4 ib = g_idx[k0 + 1];
    float2 v2 = ((const float2*)gxv)[p];

    const float4* Bv = (const float4*)g_B;
    float4 xa0 = Bv[ia.x * DV + j];
    float4 xa1 = Bv[ia.z * DV + j];
    float4 xb0 = Bv[ib.x * DV + j];
    float4 xb1 = Bv[ib.z * DV + j];

    if (LAYER0) {
        int2 c2 = ((const int2*)g_cidx)[p];
        const float4* cva = (const float4*)cat + c2.x * 32;
        const float4* cvb = (const float4*)cat + c2.y * 32;
        float4 ca0 = cva[j],      cb0 = cvb[j];
        float4 ca1 = cva[16 + j], cb1 = cvb[16 + j];
        xa0.x += ca0.x; xa0.y += ca0.y; xa0.z += ca0.z; xa0.w += ca0.w;
        xa1.x += ca1.x; xa1.y += ca1.y; xa1.z += ca1.z; xa1.w += ca1.w;
        xb0.x += cb0.x; xb0.y += cb0.y; xb0.z += cb0.z; xb0.w += cb0.w;
        xb1.x += cb1.x; xb1.y += cb1.y; xb1.z += cb1.z; xb1.w += cb1.w;
    }
    float va = v2.x, vb = v2.y;
    float4 ya0 = make_float4(va * xa0.x, va * xa0.y, va * xa0.z, va * xa0.w);
    float4 ya1 = make_float4(va * xa1.x, va * xa1.y, va * xa1.z, va * xa1.w);
    float4 yb0 = make_float4(vb * xb0.x, vb * xb0.y, vb * xb0.z, vb * xb0.w);
    float4 yb1 = make_float4(vb * xb1.x, vb * xb1.y, vb * xb1.z, vb * xb1.w);
    float4* Uv = (float4*)g_U;
    red_add_f32x4(Uv + ia.y * DV + j, ya0);
    red_add_f32x4(Uv + ia.w * DV + j, ya1);
    red_add_f32x4(Uv + ib.y * DV + j, yb0);
    red_add_f32x4(Uv + ib.w * DV + j, yb1);
}

// A = 0.5 * (U / (deg + 1e-9) + B);  acc += A;  zero B,U — 2 float4 per thread
__global__ void k_combine() {
    int t0 = (blockIdx.x * blockDim.x + threadIdx.x) * 2;
    if (t0 >= N_NODES * DV) return;
    float4 z = make_float4(0.f, 0.f, 0.f, 0.f);
    #pragma unroll
    for (int q = 0; q < 2; ++q) {
        int t = t0 + q;
        int n = t >> 4;
        float inv = 0.5f / (g_deg[n] + 1e-9f);
        float4 u = ((const float4*)g_U)[t];
        float4 b = ((const float4*)g_B)[t];
        float4 a;
        a.x = u.x * inv + 0.5f * b.x;
        a.y = u.y * inv + 0.5f * b.y;
        a.z = u.z * inv + 0.5f * b.z;
        a.w = u.w * inv + 0.5f * b.w;
        ((float4*)g_A)[t] = a;
        float4 ac = ((float4*)g_acc)[t];
        ac.x += a.x; ac.y += a.y; ac.z += a.z; ac.w += a.w;
        ((float4*)g_acc)[t] = ac;
        ((float4*)g_B)[t] = z;
        ((float4*)g_U)[t] = z;
    }
}

// gamma[b] = dot(acc[users[b]], acc[50000+items[b]]) / 9   (mean over 3 layers)
__global__ void k_dot(const int* __restrict__ users, const int* __restrict__ items,
                      float* __restrict__ out) {
    int t = blockIdx.x * blockDim.x + threadIdx.x;
    int b = t >> 5;
    if (b >= BATCH) return;
    int lane = t & 31;
    const float2* au = (const float2*)(g_acc + (size_t)users[b] * D);
    const float2* ai = (const float2*)(g_acc + (size_t)(NUM_USERS + items[b]) * D);
    float2 x = au[lane], y = ai[lane];
    float s = x.x * y.x + x.y * y.y;
    #pragma unroll
    for (int o = 16; o; o >>= 1) s += __shfl_down_sync(0xffffffffu, s, o);
    if (lane == 0) out[b] = s * (1.f / 9.f);
}

extern "C" void kernel_launch(void* const* d_in, const int* in_sizes, int n_in,
                              void* d_out, int out_size) {
    const float* user_emb = (const float*)d_in[0];
    const float* item_emb = (const float*)d_in[1];
    const float* cat_emb  = (const float*)d_in[2];
    const float* g_vals   = (const float*)d_in[3];
    const float* gx_vals  = (const float*)d_in[4];
    const int*   g_rows   = (const int*)d_in[5];
    const int*   g_cols   = (const int*)d_in[6];
    const int*   gx_rows  = (const int*)d_in[7];
    const int*   gx_cols  = (const int*)d_in[8];
    const int*   tu       = (const int*)d_in[9];
    const int*   ti       = (const int*)d_in[10];
    const int*   i2c      = (const int*)d_in[11];
    const int*   users    = (const int*)d_in[12];
    const int*   items    = (const int*)d_in[13];
    float* out = (float*)d_out;

    const int TB = 256;
    int node_grid = (N_NODES * DV + TB - 1) / TB;            // 6250
    int comb_grid = (N_NODES * DV / 2 + TB - 1) / TB;        // 3125
    int deg_grid  = (N_EDGES + TB - 1) / TB;                 // 1954
    int prep_grid = (NNZ_GX + TB - 1) / TB;                  // 7813
    int g_grid    = (NNZ_G / 2 * 16) / TB;                   // 31250
    int gx_grid   = (NNZ_GX / 2 * 16) / TB;                  // 62500
    int dot_grid  = (BATCH * 32 + TB - 1) / TB;              // 1024

    k_init<<<node_grid, TB>>>(user_emb, item_emb);
    k_deg<<<deg_grid, TB>>>(tu, ti);
    k_prep<<<prep_grid, TB>>>(gx_rows, gx_cols, tu, ti, i2c);

    for (int L = 0; L < 3; ++L) {
        k_spmm_g<<<g_grid, TB>>>(g_rows, g_cols, g_vals);
        if (L == 0) k_gx<1><<<gx_grid, TB>>>(gx_vals, cat_emb);
        else        k_gx<0><<<gx_grid, TB>>>(gx_vals, cat_emb);
        k_combine<<<comb_grid, TB>>>();
    }
    k_dot<<<dot_grid, TB>>>(users, items, out);
}